// round 1
// baseline (speedup 1.0000x reference)
#include <cuda_runtime.h>

typedef unsigned long long ULL;

// ---------------- device scratch (allocation-free rule: __device__ globals) ----
__device__ __align__(16) float g_planes[3 * 32 * 32 * 64]; // [plane][y][x][c]
__device__ __align__(16) float g_w1p[64 * 128];            // [kp][j][2] pairs, kp<32
__device__ __align__(16) float g_w2p[128 * 128];           // [kp][j][2] pairs, kp<64

// ---------------- packed fp32x2 helpers --------------------------------------
__device__ __forceinline__ ULL fma2(ULL a, ULL b, ULL c) {
    ULL d;
    asm("fma.rn.f32x2 %0, %1, %2, %3;" : "=l"(d) : "l"(a), "l"(b), "l"(c));
    return d;
}
__device__ __forceinline__ float2 upk(ULL v) {
    float2 r;
    asm("mov.b64 {%0, %1}, %2;" : "=f"(r.x), "=f"(r.y) : "l"(v));
    return r;
}

// ---------------- prep: transpose planes to channel-last, pack weights k-major
__global__ void prep_kernel(const float* __restrict__ pxy, const float* __restrict__ pyz,
                            const float* __restrict__ pxz, const float* __restrict__ w1,
                            const float* __restrict__ w2) {
    int idx = blockIdx.x * 256 + threadIdx.x;
    if (idx < 196608) {
        int pl = idx >> 16;
        int r  = idx & 65535;          // source linear over (c,y,x)
        const float* src = (pl == 0) ? pxy : ((pl == 1) ? pyz : pxz);
        float v = src[r];
        int c = r >> 10;
        int y = (r >> 5) & 31;
        int x = r & 31;
        g_planes[(pl << 16) + (((y << 5) + x) << 6) + c] = v;
    } else if (idx < 196608 + 8192) {
        int i = idx - 196608;          // w1 is [j=128][k=64]
        int j = i >> 6, k = i & 63;
        g_w1p[(k >> 1) * 256 + j * 2 + (k & 1)] = w1[i];
    } else if (idx < 196608 + 8192 + 16384) {
        int i = idx - (196608 + 8192); // w2 is [j=128][k=128]
        int j = i >> 7, k = i & 127;
        g_w2p[(k >> 1) * 256 + j * 2 + (k & 1)] = w2[i];
    }
}

// ---------------- bilinear sample: 2 channels per lane (channel-last planes) --
__device__ __forceinline__ float2 samp2(const float* __restrict__ base, float gx, float gy) {
    float x = (gx + 1.0f) * 15.5f;   // bit-identical to ((gx+1)*0.5)*31
    float y = (gy + 1.0f) * 15.5f;
    float xf = floorf(x), yf = floorf(y);
    int ix = (int)xf, iy = (int)yf;
    float wx1 = x - xf, wy1 = y - yf;
    float wx0 = 1.0f - wx1, wy0 = 1.0f - wy1;
    float2 acc = make_float2(0.0f, 0.0f);
    if ((unsigned)ix < 32u && (unsigned)iy < 32u) {
        float w = wx0 * wy0;
        float2 v = *(const float2*)(base + (((iy << 5) + ix) << 6));
        acc.x = fmaf(w, v.x, acc.x); acc.y = fmaf(w, v.y, acc.y);
    }
    if ((unsigned)(ix + 1) < 32u && (unsigned)iy < 32u) {
        float w = wx1 * wy0;
        float2 v = *(const float2*)(base + (((iy << 5) + ix + 1) << 6));
        acc.x = fmaf(w, v.x, acc.x); acc.y = fmaf(w, v.y, acc.y);
    }
    if ((unsigned)ix < 32u && (unsigned)(iy + 1) < 32u) {
        float w = wx0 * wy1;
        float2 v = *(const float2*)(base + ((((iy + 1) << 5) + ix) << 6));
        acc.x = fmaf(w, v.x, acc.x); acc.y = fmaf(w, v.y, acc.y);
    }
    if ((unsigned)(ix + 1) < 32u && (unsigned)(iy + 1) < 32u) {
        float w = wx1 * wy1;
        float2 v = *(const float2*)(base + ((((iy + 1) << 5) + ix + 1) << 6));
        acc.x = fmaf(w, v.x, acc.x); acc.y = fmaf(w, v.y, acc.y);
    }
    return acc;
}

// ---------------- fused: sample -> 64x128 -> 128x128 -> 128x1 -----------------
// 256 threads, 64 points/block. Warp w owns points [8w, 8w+8); lane owns 4
// contiguous output neurons (j0=4*lane). Accumulators packed fp32x2 over K.
__global__ __launch_bounds__(256, 1) void fused_kernel(
    const float* __restrict__ coords,
    const float* __restrict__ b1, const float* __restrict__ b2,
    const float* __restrict__ w3, const float* __restrict__ b3,
    float* __restrict__ out)
{
    extern __shared__ float smem[];
    float* sw2 = smem;           // 16384 floats  [kp<64][j][2]
    float* sw1 = smem + 16384;   //  8192 floats  [kp<32][j][2]
    float* sf  = smem + 24576;   //  4096 floats  [p=64][c=64]
    float* sh1 = smem + 28672;   //  8192 floats  [p=64][j=128]
    float* sb1 = smem + 36864;   //   128
    float* sb2 = smem + 36992;   //   128
    float* sw3 = smem + 37120;   //   128   -> total 37248 floats = 148992 B

    int tid = threadIdx.x;

    // stage weights (linear, coalesced, conflict-free — already packed)
    {
        float4* d2 = (float4*)sw2; const float4* s2 = (const float4*)g_w2p;
        #pragma unroll 4
        for (int i = tid; i < 4096; i += 256) d2[i] = s2[i];
        float4* d1 = (float4*)sw1; const float4* s1 = (const float4*)g_w1p;
        #pragma unroll 2
        for (int i = tid; i < 2048; i += 256) d1[i] = s1[i];
        if (tid < 128) { sb1[tid] = b1[tid]; sb2[tid] = b2[tid]; sw3[tid] = w3[tid]; }
    }

    int lane = tid & 31, wid = tid >> 5;
    int pBase = wid * 8;
    int mBase = blockIdx.x * 64;

    // -------- sampling: warp's 8 points, 2 channels per lane ----------------
    #pragma unroll
    for (int p = 0; p < 8; p++) {
        int m = mBase + pBase + p;
        float c0 = coords[3 * m], c1 = coords[3 * m + 1], c2 = coords[3 * m + 2];
        const float* bs = g_planes + 2 * lane;
        float2 fxy = samp2(bs,          c0, c1);
        float2 fyz = samp2(bs + 65536,  c1, c2);
        float2 fxz = samp2(bs + 131072, c0, c2);
        float2 ft;
        ft.x = fxy.x * fyz.x * fxz.x;
        ft.y = fxy.y * fyz.y * fxz.y;
        *(float2*)&sf[(pBase + p) * 64 + 2 * lane] = ft;
    }
    __syncthreads();

    int j0 = lane * 4;
    ULL acc[8][4];

    // -------- layer 1: K=64 (32 pairs) --------------------------------------
    #pragma unroll
    for (int p = 0; p < 8; p++)
        #pragma unroll
        for (int q = 0; q < 4; q++) acc[p][q] = 0ull;

    #pragma unroll 2
    for (int kp = 0; kp < 32; kp += 2) {
        const float* wrow = sw1 + kp * 256 + j0 * 2;
        ulonglong2 wA = *(const ulonglong2*)(wrow);        // j0, j0+1 @ kp
        ulonglong2 wB = *(const ulonglong2*)(wrow + 4);    // j0+2, j0+3 @ kp
        ulonglong2 wC = *(const ulonglong2*)(wrow + 256);  // @ kp+1
        ulonglong2 wD = *(const ulonglong2*)(wrow + 260);
        #pragma unroll
        for (int p = 0; p < 8; p++) {
            ulonglong2 f = *(const ulonglong2*)(sf + (pBase + p) * 64 + 2 * kp); // broadcast
            acc[p][0] = fma2(wA.x, f.x, acc[p][0]);
            acc[p][1] = fma2(wA.y, f.x, acc[p][1]);
            acc[p][2] = fma2(wB.x, f.x, acc[p][2]);
            acc[p][3] = fma2(wB.y, f.x, acc[p][3]);
            acc[p][0] = fma2(wC.x, f.y, acc[p][0]);
            acc[p][1] = fma2(wC.y, f.y, acc[p][1]);
            acc[p][2] = fma2(wD.x, f.y, acc[p][2]);
            acc[p][3] = fma2(wD.y, f.y, acc[p][3]);
        }
    }
    {
        float4 bv = *(const float4*)&sb1[j0];
        #pragma unroll
        for (int p = 0; p < 8; p++) {
            float2 a0 = upk(acc[p][0]), a1 = upk(acc[p][1]);
            float2 a2 = upk(acc[p][2]), a3 = upk(acc[p][3]);
            float4 h;
            h.x = fmaxf(a0.x + a0.y + bv.x, 0.0f);
            h.y = fmaxf(a1.x + a1.y + bv.y, 0.0f);
            h.z = fmaxf(a2.x + a2.y + bv.z, 0.0f);
            h.w = fmaxf(a3.x + a3.y + bv.w, 0.0f);
            *(float4*)&sh1[(pBase + p) * 128 + j0] = h;   // conflict-free
        }
    }
    __syncwarp();

    // -------- layer 2: K=128 (64 pairs) --------------------------------------
    #pragma unroll
    for (int p = 0; p < 8; p++)
        #pragma unroll
        for (int q = 0; q < 4; q++) acc[p][q] = 0ull;

    #pragma unroll 2
    for (int kp = 0; kp < 64; kp += 2) {
        const float* wrow = sw2 + kp * 256 + j0 * 2;
        ulonglong2 wA = *(const ulonglong2*)(wrow);
        ulonglong2 wB = *(const ulonglong2*)(wrow + 4);
        ulonglong2 wC = *(const ulonglong2*)(wrow + 256);
        ulonglong2 wD = *(const ulonglong2*)(wrow + 260);
        #pragma unroll
        for (int p = 0; p < 8; p++) {
            ulonglong2 f = *(const ulonglong2*)(sh1 + (pBase + p) * 128 + 2 * kp); // broadcast
            acc[p][0] = fma2(wA.x, f.x, acc[p][0]);
            acc[p][1] = fma2(wA.y, f.x, acc[p][1]);
            acc[p][2] = fma2(wB.x, f.x, acc[p][2]);
            acc[p][3] = fma2(wB.y, f.x, acc[p][3]);
            acc[p][0] = fma2(wC.x, f.y, acc[p][0]);
            acc[p][1] = fma2(wC.y, f.y, acc[p][1]);
            acc[p][2] = fma2(wD.x, f.y, acc[p][2]);
            acc[p][3] = fma2(wD.y, f.y, acc[p][3]);
        }
    }

    // -------- layer 2 epilogue + layer 3 + warp reduction --------------------
    {
        float4 b2v = *(const float4*)&sb2[j0];
        float4 w3v = *(const float4*)&sw3[j0];
        float part[8];
        #pragma unroll
        for (int p = 0; p < 8; p++) {
            float2 a0 = upk(acc[p][0]), a1 = upk(acc[p][1]);
            float2 a2 = upk(acc[p][2]), a3 = upk(acc[p][3]);
            float h0 = fmaxf(a0.x + a0.y + b2v.x, 0.0f);
            float h1 = fmaxf(a1.x + a1.y + b2v.y, 0.0f);
            float h2 = fmaxf(a2.x + a2.y + b2v.z, 0.0f);
            float h3 = fmaxf(a3.x + a3.y + b2v.w, 0.0f);
            part[p] = h0 * w3v.x + h1 * w3v.y + h2 * w3v.z + h3 * w3v.w;
        }
        #pragma unroll
        for (int off = 16; off >= 1; off >>= 1)
            #pragma unroll
            for (int p = 0; p < 8; p++)
                part[p] += __shfl_xor_sync(0xffffffffu, part[p], off);
        if (lane == 0) {
            float bb = b3[0];
            #pragma unroll
            for (int p = 0; p < 8; p++)
                out[mBase + pBase + p] = part[p] + bb;
        }
    }
}

// ---------------- launch ------------------------------------------------------
extern "C" void kernel_launch(void* const* d_in, const int* in_sizes, int n_in,
                              void* d_out, int out_size) {
    const float* coords = (const float*)d_in[0];
    const float* pxy    = (const float*)d_in[1];
    const float* pyz    = (const float*)d_in[2];
    const float* pxz    = (const float*)d_in[3];
    const float* w1     = (const float*)d_in[4];
    const float* b1     = (const float*)d_in[5];
    const float* w2     = (const float*)d_in[6];
    const float* b2     = (const float*)d_in[7];
    const float* w3     = (const float*)d_in[8];
    const float* b3     = (const float*)d_in[9];
    float* out = (float*)d_out;

    int M = in_sizes[0] / 3;          // 1048576
    int nblk = M / 64;                // 16384

    prep_kernel<<<864, 256>>>(pxy, pyz, pxz, w1, w2);

    const int smem_bytes = 37248 * 4; // 148992
    cudaFuncSetAttribute(fused_kernel, cudaFuncAttributeMaxDynamicSharedMemorySize, smem_bytes);
    fused_kernel<<<nblk, 256, smem_bytes>>>(coords, b1, b2, w3, b3, out);
}

// round 2
// speedup vs baseline: 1.2622x; 1.2622x over previous
#include <cuda_runtime.h>

typedef unsigned long long ULL;

// ---------------- device scratch (allocation-free rule: __device__ globals) ----
__device__ __align__(16) float g_planes[3 * 32 * 32 * 64]; // [plane][y][x][c]
__device__ __align__(16) float g_w1p[64 * 128];            // [kp][j][2] pairs, kp<32
__device__ __align__(16) float g_w2p[128 * 128];           // [kp][j][2] pairs, kp<64

// ---------------- packed fp32x2 helpers --------------------------------------
__device__ __forceinline__ ULL fma2(ULL a, ULL b, ULL c) {
    ULL d;
    asm("fma.rn.f32x2 %0, %1, %2, %3;" : "=l"(d) : "l"(a), "l"(b), "l"(c));
    return d;
}
__device__ __forceinline__ float2 upk(ULL v) {
    float2 r;
    asm("mov.b64 {%0, %1}, %2;" : "=f"(r.x), "=f"(r.y) : "l"(v));
    return r;
}
// L2-only (cache-global) vector load for plane gathers: keep L1D for weights.
__device__ __forceinline__ float2 ldcg2(const float* p) {
    float2 v;
    asm("ld.global.cg.v2.f32 {%0,%1}, [%2];" : "=f"(v.x), "=f"(v.y) : "l"(p));
    return v;
}

// ---------------- prep: transpose planes to channel-last, pack weights k-major
__global__ void prep_kernel(const float* __restrict__ pxy, const float* __restrict__ pyz,
                            const float* __restrict__ pxz, const float* __restrict__ w1,
                            const float* __restrict__ w2) {
    int idx = blockIdx.x * 256 + threadIdx.x;
    if (idx < 196608) {
        int pl = idx >> 16;
        int r  = idx & 65535;          // source linear over (c,y,x)
        const float* src = (pl == 0) ? pxy : ((pl == 1) ? pyz : pxz);
        float v = src[r];
        int c = r >> 10;
        int y = (r >> 5) & 31;
        int x = r & 31;
        g_planes[(pl << 16) + (((y << 5) + x) << 6) + c] = v;
    } else if (idx < 196608 + 8192) {
        int i = idx - 196608;          // w1 is [j=128][k=64]
        int j = i >> 6, k = i & 63;
        g_w1p[(k >> 1) * 256 + j * 2 + (k & 1)] = w1[i];
    } else if (idx < 196608 + 8192 + 16384) {
        int i = idx - (196608 + 8192); // w2 is [j=128][k=128]
        int j = i >> 7, k = i & 127;
        g_w2p[(k >> 1) * 256 + j * 2 + (k & 1)] = w2[i];
    }
}

// ---------------- bilinear sample: 2 channels per lane (channel-last planes) --
__device__ __forceinline__ float2 samp2(const float* __restrict__ base, float gx, float gy) {
    float x = (gx + 1.0f) * 15.5f;   // bit-identical to ((gx+1)*0.5)*31
    float y = (gy + 1.0f) * 15.5f;
    float xf = floorf(x), yf = floorf(y);
    int ix = (int)xf, iy = (int)yf;
    float wx1 = x - xf, wy1 = y - yf;
    float wx0 = 1.0f - wx1, wy0 = 1.0f - wy1;
    float2 acc = make_float2(0.0f, 0.0f);
    if ((unsigned)ix < 32u && (unsigned)iy < 32u) {
        float w = wx0 * wy0;
        float2 v = ldcg2(base + (((iy << 5) + ix) << 6));
        acc.x = fmaf(w, v.x, acc.x); acc.y = fmaf(w, v.y, acc.y);
    }
    if ((unsigned)(ix + 1) < 32u && (unsigned)iy < 32u) {
        float w = wx1 * wy0;
        float2 v = ldcg2(base + (((iy << 5) + ix + 1) << 6));
        acc.x = fmaf(w, v.x, acc.x); acc.y = fmaf(w, v.y, acc.y);
    }
    if ((unsigned)ix < 32u && (unsigned)(iy + 1) < 32u) {
        float w = wx0 * wy1;
        float2 v = ldcg2(base + ((((iy + 1) << 5) + ix) << 6));
        acc.x = fmaf(w, v.x, acc.x); acc.y = fmaf(w, v.y, acc.y);
    }
    if ((unsigned)(ix + 1) < 32u && (unsigned)(iy + 1) < 32u) {
        float w = wx1 * wy1;
        float2 v = ldcg2(base + ((((iy + 1) << 5) + ix + 1) << 6));
        acc.x = fmaf(w, v.x, acc.x); acc.y = fmaf(w, v.y, acc.y);
    }
    return acc;
}

// ---------------- fused: sample -> 64x128 -> 128x128 -> 128x1 -----------------
// 256 threads, 64 points/block, 2 blocks/SM. Warp w owns points [8w, 8w+8);
// lane owns 4 contiguous output neurons (j0=4*lane). Weights come from L1-cached
// global (packed k-major); only activations live in smem (~50KB/block).
__global__ __launch_bounds__(256, 2) void fused_kernel(
    const float* __restrict__ coords,
    const float* __restrict__ b1, const float* __restrict__ b2,
    const float* __restrict__ w3, const float* __restrict__ b3,
    float* __restrict__ out)
{
    extern __shared__ float smem[];
    float* sf  = smem;           //  4096 floats  [p=64][c=64]
    float* sh1 = smem + 4096;    //  8192 floats  [p=64][j=128]
    float* sb1 = smem + 12288;   //   128
    float* sb2 = smem + 12416;   //   128
    float* sw3 = smem + 12544;   //   128  -> total 12672 floats = 50688 B

    int tid = threadIdx.x;
    if (tid < 128) { sb1[tid] = b1[tid]; sb2[tid] = b2[tid]; sw3[tid] = w3[tid]; }

    int lane = tid & 31, wid = tid >> 5;
    int pBase = wid * 8;
    int mBase = blockIdx.x * 64;

    // -------- sampling: warp's 8 points, 2 channels per lane ----------------
    #pragma unroll
    for (int p = 0; p < 8; p++) {
        int m = mBase + pBase + p;
        float c0 = coords[3 * m], c1 = coords[3 * m + 1], c2 = coords[3 * m + 2];
        const float* bs = g_planes + 2 * lane;
        float2 fxy = samp2(bs,          c0, c1);
        float2 fyz = samp2(bs + 65536,  c1, c2);
        float2 fxz = samp2(bs + 131072, c0, c2);
        float2 ft;
        ft.x = fxy.x * fyz.x * fxz.x;
        ft.y = fxy.y * fyz.y * fxz.y;
        *(float2*)&sf[(pBase + p) * 64 + 2 * lane] = ft;
    }
    __syncthreads();

    int j0 = lane * 4;
    ULL acc[8][4];

    // -------- layer 1: K=64 (32 pairs), weights from L1-cached global --------
    #pragma unroll
    for (int p = 0; p < 8; p++)
        #pragma unroll
        for (int q = 0; q < 4; q++) acc[p][q] = 0ull;

    #pragma unroll 2
    for (int kp = 0; kp < 32; kp += 2) {
        const float* wrow = g_w1p + kp * 256 + j0 * 2;
        ulonglong2 wA = __ldg((const ulonglong2*)(wrow));        // j0,j0+1 @ kp
        ulonglong2 wB = __ldg((const ulonglong2*)(wrow + 4));    // j0+2,j0+3 @ kp
        ulonglong2 wC = __ldg((const ulonglong2*)(wrow + 256));  // @ kp+1
        ulonglong2 wD = __ldg((const ulonglong2*)(wrow + 260));
        #pragma unroll
        for (int p = 0; p < 8; p++) {
            ulonglong2 f = *(const ulonglong2*)(sf + (pBase + p) * 64 + 2 * kp); // broadcast
            acc[p][0] = fma2(wA.x, f.x, acc[p][0]);
            acc[p][1] = fma2(wA.y, f.x, acc[p][1]);
            acc[p][2] = fma2(wB.x, f.x, acc[p][2]);
            acc[p][3] = fma2(wB.y, f.x, acc[p][3]);
            acc[p][0] = fma2(wC.x, f.y, acc[p][0]);
            acc[p][1] = fma2(wC.y, f.y, acc[p][1]);
            acc[p][2] = fma2(wD.x, f.y, acc[p][2]);
            acc[p][3] = fma2(wD.y, f.y, acc[p][3]);
        }
    }
    {
        float4 bv = *(const float4*)&sb1[j0];
        #pragma unroll
        for (int p = 0; p < 8; p++) {
            float2 a0 = upk(acc[p][0]), a1 = upk(acc[p][1]);
            float2 a2 = upk(acc[p][2]), a3 = upk(acc[p][3]);
            float4 h;
            h.x = fmaxf(a0.x + a0.y + bv.x, 0.0f);
            h.y = fmaxf(a1.x + a1.y + bv.y, 0.0f);
            h.z = fmaxf(a2.x + a2.y + bv.z, 0.0f);
            h.w = fmaxf(a3.x + a3.y + bv.w, 0.0f);
            *(float4*)&sh1[(pBase + p) * 128 + j0] = h;   // conflict-free
        }
    }
    __syncwarp();

    // -------- layer 2: K=128 (64 pairs) --------------------------------------
    #pragma unroll
    for (int p = 0; p < 8; p++)
        #pragma unroll
        for (int q = 0; q < 4; q++) acc[p][q] = 0ull;

    #pragma unroll 2
    for (int kp = 0; kp < 64; kp += 2) {
        const float* wrow = g_w2p + kp * 256 + j0 * 2;
        ulonglong2 wA = __ldg((const ulonglong2*)(wrow));
        ulonglong2 wB = __ldg((const ulonglong2*)(wrow + 4));
        ulonglong2 wC = __ldg((const ulonglong2*)(wrow + 256));
        ulonglong2 wD = __ldg((const ulonglong2*)(wrow + 260));
        #pragma unroll
        for (int p = 0; p < 8; p++) {
            ulonglong2 f = *(const ulonglong2*)(sh1 + (pBase + p) * 128 + 2 * kp); // broadcast
            acc[p][0] = fma2(wA.x, f.x, acc[p][0]);
            acc[p][1] = fma2(wA.y, f.x, acc[p][1]);
            acc[p][2] = fma2(wB.x, f.x, acc[p][2]);
            acc[p][3] = fma2(wB.y, f.x, acc[p][3]);
            acc[p][0] = fma2(wC.x, f.y, acc[p][0]);
            acc[p][1] = fma2(wC.y, f.y, acc[p][1]);
            acc[p][2] = fma2(wD.x, f.y, acc[p][2]);
            acc[p][3] = fma2(wD.y, f.y, acc[p][3]);
        }
    }

    // -------- layer 2 epilogue + layer 3 + warp reduction --------------------
    {
        float4 b2v = *(const float4*)&sb2[j0];
        float4 w3v = *(const float4*)&sw3[j0];
        float part[8];
        #pragma unroll
        for (int p = 0; p < 8; p++) {
            float2 a0 = upk(acc[p][0]), a1 = upk(acc[p][1]);
            float2 a2 = upk(acc[p][2]), a3 = upk(acc[p][3]);
            float h0 = fmaxf(a0.x + a0.y + b2v.x, 0.0f);
            float h1 = fmaxf(a1.x + a1.y + b2v.y, 0.0f);
            float h2 = fmaxf(a2.x + a2.y + b2v.z, 0.0f);
            float h3 = fmaxf(a3.x + a3.y + b2v.w, 0.0f);
            part[p] = h0 * w3v.x + h1 * w3v.y + h2 * w3v.z + h3 * w3v.w;
        }
        #pragma unroll
        for (int off = 16; off >= 1; off >>= 1)
            #pragma unroll
            for (int p = 0; p < 8; p++)
                part[p] += __shfl_xor_sync(0xffffffffu, part[p], off);
        if (lane == 0) {
            float bb = b3[0];
            #pragma unroll
            for (int p = 0; p < 8; p++)
                out[mBase + pBase + p] = part[p] + bb;
        }
    }
}

// ---------------- launch ------------------------------------------------------
extern "C" void kernel_launch(void* const* d_in, const int* in_sizes, int n_in,
                              void* d_out, int out_size) {
    const float* coords = (const float*)d_in[0];
    const float* pxy    = (const float*)d_in[1];
    const float* pyz    = (const float*)d_in[2];
    const float* pxz    = (const float*)d_in[3];
    const float* w1     = (const float*)d_in[4];
    const float* b1     = (const float*)d_in[5];
    const float* w2     = (const float*)d_in[6];
    const float* b2     = (const float*)d_in[7];
    const float* w3     = (const float*)d_in[8];
    const float* b3     = (const float*)d_in[9];
    float* out = (float*)d_out;

    int M = in_sizes[0] / 3;          // 1048576
    int nblk = M / 64;                // 16384

    prep_kernel<<<864, 256>>>(pxy, pyz, pxz, w1, w2);

    const int smem_bytes = 12672 * 4; // 50688
    cudaFuncSetAttribute(fused_kernel, cudaFuncAttributeMaxDynamicSharedMemorySize, smem_bytes);
    fused_kernel<<<nblk, 256, smem_bytes>>>(coords, b1, b2, w3, b3, out);
}

// round 5
// speedup vs baseline: 2.2253x; 1.7630x over previous
#include <cuda_runtime.h>
#include <cuda_fp16.h>
#include <cstdint>

typedef uint32_t u32;

// ---------------- device scratch (allocation-free rule) ----------------------
__device__ __align__(16) float g_planes[3 * 32 * 32 * 64]; // [plane][y][x][c]
__device__ __align__(16) u32   g_w1f[16 * 4 * 32 * 4];     // [nt][ks][lane][w] frag-packed
__device__ __align__(16) u32   g_w2f[16 * 8 * 32 * 4];     // [nt][ks][lane][w]

#define NW 12
// dynamic smem layout (floats/u32 units):
//   sA1: NW*4*8*32 u32 = 12288 u32  (49152 B)
//   sB1: 128 f, sB2: 128 f, sW3: 128 f
#define SMEM_U32_TOTAL (NW * 4 * 8 * 32 + 384)
#define SMEM_BYTES (SMEM_U32_TOTAL * 4)

// ---------------- helpers ----------------------------------------------------
__device__ __forceinline__ float2 ldcg2(const float* p) {
    float2 v; asm("ld.global.cg.v2.f32 {%0,%1}, [%2];" : "=f"(v.x), "=f"(v.y) : "l"(p)); return v;
}
__device__ __forceinline__ u32 pk2(float x, float y) {
    __half2 h = __halves2half2(__float2half_rn(x), __float2half_rn(y));
    return *(u32*)&h;
}
__device__ __forceinline__ float rf16(float x) {
    return __half2float(__float2half_rn(x));
}
__device__ __forceinline__ void mma16(float* c, const u32* a, u32 b0, u32 b1) {
    asm volatile("mma.sync.aligned.m16n8k16.row.col.f32.f16.f16.f32 "
        "{%0,%1,%2,%3}, {%4,%5,%6,%7}, {%8,%9}, {%0,%1,%2,%3};"
        : "+f"(c[0]), "+f"(c[1]), "+f"(c[2]), "+f"(c[3])
        : "r"(a[0]), "r"(a[1]), "r"(a[2]), "r"(a[3]), "r"(b0), "r"(b1));
}

// ---------------- prep: planes channel-last; weights fragment-packed hi/lo ----
__global__ void prep_kernel(const float* __restrict__ pxy, const float* __restrict__ pyz,
                            const float* __restrict__ pxz, const float* __restrict__ w1,
                            const float* __restrict__ w2) {
    int idx = blockIdx.x * 256 + threadIdx.x;
    if (idx < 196608) {
        int pl = idx >> 16;
        int r  = idx & 65535;
        const float* src = (pl == 0) ? pxy : ((pl == 1) ? pyz : pxz);
        float v = src[r];
        int c = r >> 10, y = (r >> 5) & 31, x = r & 31;
        g_planes[(pl << 16) + (((y << 5) + x) << 6) + c] = v;
    } else if (idx < 196608 + 8192) {
        int i = idx - 196608;                       // w1: [n=128][k=64]
        int w = i & 3, lane = (i >> 2) & 31, ks = (i >> 7) & 3, nt = i >> 9;
        int g = lane >> 2, t = lane & 3;
        int n = nt * 8 + g;
        int k0 = ks * 16 + ((w & 1) << 3) + t * 2;
        float v0 = w1[n * 64 + k0], v1 = w1[n * 64 + k0 + 1];
        u32 val = (w < 2) ? pk2(v0, v1) : pk2(v0 - rf16(v0), v1 - rf16(v1));
        g_w1f[i] = val;
    } else if (idx < 196608 + 8192 + 16384) {
        int i = idx - (196608 + 8192);              // w2: [n=128][k=128]
        int w = i & 3, lane = (i >> 2) & 31, ks = (i >> 7) & 7, nt = i >> 10;
        int g = lane >> 2, t = lane & 3;
        int n = nt * 8 + g;
        int k0 = ks * 16 + ((w & 1) << 3) + t * 2;
        float v0 = w2[n * 128 + k0], v1 = w2[n * 128 + k0 + 1];
        u32 val = (w < 2) ? pk2(v0, v1) : pk2(v0 - rf16(v0), v1 - rf16(v1));
        g_w2f[i] = val;
    }
}

// ---------------- bilinear sample: 2 channels per lane -----------------------
__device__ __forceinline__ float2 samp2(const float* __restrict__ base, float gx, float gy) {
    float x = (gx + 1.0f) * 15.5f;
    float y = (gy + 1.0f) * 15.5f;
    float xf = floorf(x), yf = floorf(y);
    int ix = (int)xf, iy = (int)yf;
    float wx1 = x - xf, wy1 = y - yf;
    float wx0 = 1.0f - wx1, wy0 = 1.0f - wy1;
    float2 acc = make_float2(0.0f, 0.0f);
    if ((unsigned)ix < 32u && (unsigned)iy < 32u) {
        float w = wx0 * wy0; float2 v = ldcg2(base + (((iy << 5) + ix) << 6));
        acc.x = fmaf(w, v.x, acc.x); acc.y = fmaf(w, v.y, acc.y);
    }
    if ((unsigned)(ix + 1) < 32u && (unsigned)iy < 32u) {
        float w = wx1 * wy0; float2 v = ldcg2(base + (((iy << 5) + ix + 1) << 6));
        acc.x = fmaf(w, v.x, acc.x); acc.y = fmaf(w, v.y, acc.y);
    }
    if ((unsigned)ix < 32u && (unsigned)(iy + 1) < 32u) {
        float w = wx0 * wy1; float2 v = ldcg2(base + ((((iy + 1) << 5) + ix) << 6));
        acc.x = fmaf(w, v.x, acc.x); acc.y = fmaf(w, v.y, acc.y);
    }
    if ((unsigned)(ix + 1) < 32u && (unsigned)(iy + 1) < 32u) {
        float w = wx1 * wy1; float2 v = ldcg2(base + ((((iy + 1) << 5) + ix + 1) << 6));
        acc.x = fmaf(w, v.x, acc.x); acc.y = fmaf(w, v.y, acc.y);
    }
    return acc;
}

// ---------------- persistent warp-autonomous fused kernel --------------------
__global__ __launch_bounds__(384, 1) void fused_kernel(
    const float* __restrict__ coords,
    const float* __restrict__ b1, const float* __restrict__ b2,
    const float* __restrict__ w3, const float* __restrict__ b3,
    float* __restrict__ out, int nslices)
{
    extern __shared__ __align__(16) u32 dsm[];
    // sA1 view: [warp][ks][word 0-3 hi,4-7 lo][lane]
    u32 (*sA1)[4][8][32] = (u32 (*)[4][8][32])dsm;
    float* sB1 = (float*)(dsm + NW * 4 * 8 * 32);
    float* sB2 = sB1 + 128;
    float* sW3 = sB2 + 128;

    int tid = threadIdx.x, lane = tid & 31, wid = tid >> 5;
    if (tid < 128) { sB1[tid] = b1[tid]; sB2[tid] = b2[tid]; sW3[tid] = w3[tid]; }
    __syncthreads();

    int g = lane >> 2, t = lane & 3;
    float bb3 = __ldg(b3);
    const float* bs = g_planes + 2 * lane;
    const uint4* w1f = (const uint4*)g_w1f;
    const uint4* w2f = (const uint4*)g_w2f;

    // sampler-side A1 addressing (lane covers channels 2l, 2l+1)
    int ks_s     = lane >> 3;
    int whi_base = ((lane >> 2) & 1) * 2;
    int tl       = lane & 3;

    int totalWarps = gridDim.x * NW;
    for (int s = blockIdx.x * NW + wid; s < nslices; s += totalWarps) {
        __syncwarp();
        int pbase = s * 16;

        // ---- sampling: 16 points, fragment-packed hi/lo stores --------------
        #pragma unroll 2
        for (int r = 0; r < 16; r++) {
            const float* cp = coords + 3 * (pbase + r);
            float c0 = __ldg(cp), c1 = __ldg(cp + 1), c2 = __ldg(cp + 2);
            float2 fxy = samp2(bs,          c0, c1);
            float2 fyz = samp2(bs + 65536,  c1, c2);
            float2 fxz = samp2(bs + 131072, c0, c2);
            float f0 = fxy.x * fyz.x * fxz.x;
            float f1 = fxy.y * fyz.y * fxz.y;
            int whi = (r >> 3) + whi_base;
            int tgt = (r & 7) * 4 + tl;
            sA1[wid][ks_s][whi][tgt]     = pk2(f0, f1);
            sA1[wid][ks_s][whi + 4][tgt] = pk2(f0 - rf16(f0), f1 - rf16(f1));
        }
        __syncwarp();

        // ---- load A1 fragments ---------------------------------------------
        u32 ah[4][4], al[4][4];
        #pragma unroll
        for (int ks = 0; ks < 4; ks++)
            #pragma unroll
            for (int w = 0; w < 4; w++) {
                ah[ks][w] = sA1[wid][ks][w][lane];
                al[ks][w] = sA1[wid][ks][w + 4][lane];
            }

        // ---- layer 1: 16 n-tiles, K=64, 3-pass fp16 split -------------------
        u32 a2h[8][4], a2l[8][4];
        #pragma unroll 1
        for (int nt = 0; nt < 16; nt++) {
            float c[4] = {0.f, 0.f, 0.f, 0.f};
            #pragma unroll
            for (int ks = 0; ks < 4; ks++) {
                uint4 B = __ldg(w1f + (nt * 4 + ks) * 32 + lane);
                mma16(c, ah[ks], B.x, B.y);
                mma16(c, al[ks], B.x, B.y);
                mma16(c, ah[ks], B.z, B.w);
            }
            // epilogue1: bias+relu, split to A2 fragments (lane-local!)
            int n = nt * 8 + t * 2;
            float h0 = fmaxf(c[0] + sB1[n], 0.f);
            float h1 = fmaxf(c[1] + sB1[n + 1], 0.f);
            float h2 = fmaxf(c[2] + sB1[n], 0.f);
            float h3 = fmaxf(c[3] + sB1[n + 1], 0.f);
            int ks2 = nt >> 1, w0 = (nt & 1) * 2;
            a2h[ks2][w0]     = pk2(h0, h1);
            a2h[ks2][w0 + 1] = pk2(h2, h3);
            a2l[ks2][w0]     = pk2(h0 - rf16(h0), h1 - rf16(h1));
            a2l[ks2][w0 + 1] = pk2(h2 - rf16(h2), h3 - rf16(h3));
        }

        // ---- layer 2: 16 n-tiles, K=128, 3-pass + fused layer-3 dot ---------
        float plo = 0.f, phi = 0.f;
        #pragma unroll 1
        for (int nt = 0; nt < 16; nt++) {
            float c[4] = {0.f, 0.f, 0.f, 0.f};
            #pragma unroll
            for (int ks = 0; ks < 8; ks++) {
                uint4 B = __ldg(w2f + (nt * 8 + ks) * 32 + lane);
                mma16(c, a2h[ks], B.x, B.y);
                mma16(c, a2l[ks], B.x, B.y);
                mma16(c, a2h[ks], B.z, B.w);
            }
            int n = nt * 8 + t * 2;
            float w30 = sW3[n], w31 = sW3[n + 1];
            float bb0 = sB2[n], bb1 = sB2[n + 1];
            plo = fmaf(fmaxf(c[0] + bb0, 0.f), w30, plo);
            plo = fmaf(fmaxf(c[1] + bb1, 0.f), w31, plo);
            phi = fmaf(fmaxf(c[2] + bb0, 0.f), w30, phi);
            phi = fmaf(fmaxf(c[3] + bb1, 0.f), w31, phi);
        }
        plo += __shfl_xor_sync(0xffffffffu, plo, 1);
        plo += __shfl_xor_sync(0xffffffffu, plo, 2);
        phi += __shfl_xor_sync(0xffffffffu, phi, 1);
        phi += __shfl_xor_sync(0xffffffffu, phi, 2);
        if (t == 0) {
            out[pbase + g]     = plo + bb3;
            out[pbase + g + 8] = phi + bb3;
        }
    }
}

// ---------------- launch ------------------------------------------------------
extern "C" void kernel_launch(void* const* d_in, const int* in_sizes, int n_in,
                              void* d_out, int out_size) {
    const float* coords = (const float*)d_in[0];
    const float* pxy    = (const float*)d_in[1];
    const float* pyz    = (const float*)d_in[2];
    const float* pxz    = (const float*)d_in[3];
    const float* w1     = (const float*)d_in[4];
    const float* b1     = (const float*)d_in[5];
    const float* w2     = (const float*)d_in[6];
    const float* b2     = (const float*)d_in[7];
    const float* w3     = (const float*)d_in[8];
    const float* b3     = (const float*)d_in[9];
    float* out = (float*)d_out;

    int M = in_sizes[0] / 3;       // 1048576
    int nslices = M / 16;          // 65536

    prep_kernel<<<864, 256>>>(pxy, pyz, pxz, w1, w2);

    int dev = 0, nsm = 148;
    cudaGetDevice(&dev);
    cudaDeviceGetAttribute(&nsm, cudaDevAttrMultiProcessorCount, dev);

    cudaFuncSetAttribute(fused_kernel, cudaFuncAttributeMaxDynamicSharedMemorySize, SMEM_BYTES);
    fused_kernel<<<nsm, 384, SMEM_BYTES>>>(coords, b1, b2, w3, b3, out, nslices);
}

// round 6
// speedup vs baseline: 3.0349x; 1.3638x over previous
#include <cuda_runtime.h>
#include <cuda_fp16.h>
#include <cstdint>

typedef uint32_t u32;

// ---------------- device scratch (allocation-free rule) ----------------------
__device__ __align__(16) float g_planes[3 * 32 * 32 * 64]; // [plane][y][x][c]
__device__ __align__(16) u32   g_w1f[16 * 4 * 32 * 4];     // [nt][ks][lane][w] frag-packed
__device__ __align__(16) u32   g_w2f[16 * 8 * 32 * 4];     // [nt][ks][lane][w]

#define NW 16
#define SMEM_U32_TOTAL (NW * 4 * 8 * 32 + 384)
#define SMEM_BYTES (SMEM_U32_TOTAL * 4)

// scaling to keep fp16 residuals out of the denormal range
#define S1      16384.0f      // feature scale (layer-1 A)
#define INV_S1  (1.0f / 16384.0f)
#define S2      4096.0f       // hidden scale (layer-2 A)
#define INV_S2  (1.0f / 4096.0f)
#define SC      2048.0f       // residual scale (both A and B lo parts)
#define INV_SC  (1.0f / 2048.0f)

// ---------------- helpers ----------------------------------------------------
__device__ __forceinline__ float2 ldcg2(const float* p) {
    float2 v; asm("ld.global.cg.v2.f32 {%0,%1}, [%2];" : "=f"(v.x), "=f"(v.y) : "l"(p)); return v;
}
__device__ __forceinline__ u32 pk2(float x, float y) {
    __half2 h = __halves2half2(__float2half_rn(x), __float2half_rn(y));
    return *(u32*)&h;
}
__device__ __forceinline__ float rf16(float x) {
    return __half2float(__float2half_rn(x));
}
__device__ __forceinline__ void mma16(float* c, const u32* a, u32 b0, u32 b1) {
    asm volatile("mma.sync.aligned.m16n8k16.row.col.f32.f16.f16.f32 "
        "{%0,%1,%2,%3}, {%4,%5,%6,%7}, {%8,%9}, {%0,%1,%2,%3};"
        : "+f"(c[0]), "+f"(c[1]), "+f"(c[2]), "+f"(c[3])
        : "r"(a[0]), "r"(a[1]), "r"(a[2]), "r"(a[3]), "r"(b0), "r"(b1));
}

// ---------------- prep: planes channel-last; weights frag-packed hi + lo*2048
__global__ void prep_kernel(const float* __restrict__ pxy, const float* __restrict__ pyz,
                            const float* __restrict__ pxz, const float* __restrict__ w1,
                            const float* __restrict__ w2) {
    int idx = blockIdx.x * 256 + threadIdx.x;
    if (idx < 196608) {
        int pl = idx >> 16;
        int r  = idx & 65535;
        const float* src = (pl == 0) ? pxy : ((pl == 1) ? pyz : pxz);
        float v = src[r];
        int c = r >> 10, y = (r >> 5) & 31, x = r & 31;
        g_planes[(pl << 16) + (((y << 5) + x) << 6) + c] = v;
    } else if (idx < 196608 + 8192) {
        int i = idx - 196608;                       // w1: [n=128][k=64]
        int w = i & 3, lane = (i >> 2) & 31, ks = (i >> 7) & 3, nt = i >> 9;
        int g = lane >> 2, t = lane & 3;
        int n = nt * 8 + g;
        int k0 = ks * 16 + ((w & 1) << 3) + t * 2;
        float v0 = w1[n * 64 + k0], v1 = w1[n * 64 + k0 + 1];
        u32 val = (w < 2) ? pk2(v0, v1)
                          : pk2((v0 - rf16(v0)) * SC, (v1 - rf16(v1)) * SC);
        g_w1f[i] = val;
    } else if (idx < 196608 + 8192 + 16384) {
        int i = idx - (196608 + 8192);              // w2: [n=128][k=128]
        int w = i & 3, lane = (i >> 2) & 31, ks = (i >> 7) & 7, nt = i >> 10;
        int g = lane >> 2, t = lane & 3;
        int n = nt * 8 + g;
        int k0 = ks * 16 + ((w & 1) << 3) + t * 2;
        float v0 = w2[n * 128 + k0], v1 = w2[n * 128 + k0 + 1];
        u32 val = (w < 2) ? pk2(v0, v1)
                          : pk2((v0 - rf16(v0)) * SC, (v1 - rf16(v1)) * SC);
        g_w2f[i] = val;
    }
}

// ---------------- bilinear sample: 2 channels per lane -----------------------
__device__ __forceinline__ float2 samp2(const float* __restrict__ base, float gx, float gy) {
    float x = (gx + 1.0f) * 15.5f;
    float y = (gy + 1.0f) * 15.5f;
    float xf = floorf(x), yf = floorf(y);
    int ix = (int)xf, iy = (int)yf;
    float wx1 = x - xf, wy1 = y - yf;
    float wx0 = 1.0f - wx1, wy0 = 1.0f - wy1;
    float2 acc = make_float2(0.0f, 0.0f);
    if ((unsigned)ix < 32u && (unsigned)iy < 32u) {
        float w = wx0 * wy0; float2 v = ldcg2(base + (((iy << 5) + ix) << 6));
        acc.x = fmaf(w, v.x, acc.x); acc.y = fmaf(w, v.y, acc.y);
    }
    if ((unsigned)(ix + 1) < 32u && (unsigned)iy < 32u) {
        float w = wx1 * wy0; float2 v = ldcg2(base + (((iy << 5) + ix + 1) << 6));
        acc.x = fmaf(w, v.x, acc.x); acc.y = fmaf(w, v.y, acc.y);
    }
    if ((unsigned)ix < 32u && (unsigned)(iy + 1) < 32u) {
        float w = wx0 * wy1; float2 v = ldcg2(base + ((((iy + 1) << 5) + ix) << 6));
        acc.x = fmaf(w, v.x, acc.x); acc.y = fmaf(w, v.y, acc.y);
    }
    if ((unsigned)(ix + 1) < 32u && (unsigned)(iy + 1) < 32u) {
        float w = wx1 * wy1; float2 v = ldcg2(base + ((((iy + 1) << 5) + ix + 1) << 6));
        acc.x = fmaf(w, v.x, acc.x); acc.y = fmaf(w, v.y, acc.y);
    }
    return acc;
}

// ---------------- persistent warp-autonomous fused kernel --------------------
__global__ __launch_bounds__(NW * 32, 1) void fused_kernel(
    const float* __restrict__ coords,
    const float* __restrict__ b1, const float* __restrict__ b2,
    const float* __restrict__ w3, const float* __restrict__ b3,
    float* __restrict__ out, int nslices)
{
    extern __shared__ __align__(16) u32 dsm[];
    u32 (*sA1)[4][8][32] = (u32 (*)[4][8][32])dsm;  // [warp][ks][word hi0-3 lo4-7][lane]
    float* sB1 = (float*)(dsm + NW * 4 * 8 * 32);
    float* sB2 = sB1 + 128;
    float* sW3 = sB2 + 128;

    int tid = threadIdx.x, lane = tid & 31, wid = tid >> 5;
    if (tid < 128) { sB1[tid] = b1[tid]; sB2[tid] = b2[tid]; sW3[tid] = w3[tid]; }
    __syncthreads();

    int g = lane >> 2, t = lane & 3;
    float bb3 = __ldg(b3);
    const float* bs = g_planes + 2 * lane;
    const uint4* w1f = (const uint4*)g_w1f;
    const uint4* w2f = (const uint4*)g_w2f;

    // sampler-side A1 addressing (lane covers channels 2l, 2l+1)
    int ks_s     = lane >> 3;
    int whi_base = ((lane >> 2) & 1) * 2;
    int tl       = lane & 3;

    int totalWarps = gridDim.x * NW;
    for (int s = blockIdx.x * NW + wid; s < nslices; s += totalWarps) {
        __syncwarp();
        int pbase = s * 16;

        // ---- sampling: 16 points, scaled hi + scaled-residual stores --------
        #pragma unroll 2
        for (int r = 0; r < 16; r++) {
            const float* cp = coords + 3 * (pbase + r);
            float c0 = __ldg(cp), c1 = __ldg(cp + 1), c2 = __ldg(cp + 2);
            float2 fxy = samp2(bs,          c0, c1);
            float2 fyz = samp2(bs + 65536,  c1, c2);
            float2 fxz = samp2(bs + 131072, c0, c2);
            float f0 = fxy.x * fyz.x * fxz.x * S1;
            float f1 = fxy.y * fyz.y * fxz.y * S1;
            int whi = (r >> 3) + whi_base;
            int tgt = (r & 7) * 4 + tl;
            sA1[wid][ks_s][whi][tgt]     = pk2(f0, f1);
            sA1[wid][ks_s][whi + 4][tgt] = pk2((f0 - rf16(f0)) * SC, (f1 - rf16(f1)) * SC);
        }
        __syncwarp();

        // ---- load A1 fragments ---------------------------------------------
        u32 ah[4][4], al[4][4];
        #pragma unroll
        for (int ks = 0; ks < 4; ks++)
            #pragma unroll
            for (int w = 0; w < 4; w++) {
                ah[ks][w] = sA1[wid][ks][w][lane];
                al[ks][w] = sA1[wid][ks][w + 4][lane];
            }

        // ---- layer 1: 16 n-tiles, K=64, scaled 3-pass split -----------------
        u32 a2h[8][4], a2l[8][4];
        #pragma unroll 2
        for (int nt = 0; nt < 16; nt++) {
            float c0[4] = {0.f, 0.f, 0.f, 0.f};
            float c1[4] = {0.f, 0.f, 0.f, 0.f};
            #pragma unroll
            for (int ks = 0; ks < 4; ks++) {
                uint4 B = __ldg(w1f + (nt * 4 + ks) * 32 + lane);
                mma16(c0, ah[ks], B.x, B.y);   // Ah*Bh
                mma16(c1, al[ks], B.x, B.y);   // (Al*SC)*Bh
                mma16(c1, ah[ks], B.z, B.w);   // Ah*(Bl*SC)
            }
            // epilogue1: combine, unscale, bias+relu, rescale+split for A2
            int n = nt * 8 + t * 2;
            float h0 = fmaxf(fmaf(fmaf(c1[0], INV_SC, c0[0]), INV_S1, sB1[n]),     0.f) * S2;
            float h1 = fmaxf(fmaf(fmaf(c1[1], INV_SC, c0[1]), INV_S1, sB1[n + 1]), 0.f) * S2;
            float h2 = fmaxf(fmaf(fmaf(c1[2], INV_SC, c0[2]), INV_S1, sB1[n]),     0.f) * S2;
            float h3 = fmaxf(fmaf(fmaf(c1[3], INV_SC, c0[3]), INV_S1, sB1[n + 1]), 0.f) * S2;
            int ks2 = nt >> 1, w0 = (nt & 1) * 2;
            a2h[ks2][w0]     = pk2(h0, h1);
            a2h[ks2][w0 + 1] = pk2(h2, h3);
            a2l[ks2][w0]     = pk2((h0 - rf16(h0)) * SC, (h1 - rf16(h1)) * SC);
            a2l[ks2][w0 + 1] = pk2((h2 - rf16(h2)) * SC, (h3 - rf16(h3)) * SC);
        }

        // ---- layer 2: 16 n-tiles, K=128, scaled 3-pass + fused layer-3 ------
        float plo = 0.f, phi = 0.f;
        #pragma unroll 2
        for (int nt = 0; nt < 16; nt++) {
            float c0[4] = {0.f, 0.f, 0.f, 0.f};
            float c1[4] = {0.f, 0.f, 0.f, 0.f};
            #pragma unroll
            for (int ks = 0; ks < 8; ks++) {
                uint4 B = __ldg(w2f + (nt * 8 + ks) * 32 + lane);
                mma16(c0, a2h[ks], B.x, B.y);
                mma16(c1, a2l[ks], B.x, B.y);
                mma16(c1, a2h[ks], B.z, B.w);
            }
            int n = nt * 8 + t * 2;
            float w30 = sW3[n], w31 = sW3[n + 1];
            float bb0 = sB2[n], bb1 = sB2[n + 1];
            float v0 = fmaf(fmaf(c1[0], INV_SC, c0[0]), INV_S2, bb0);
            float v1 = fmaf(fmaf(c1[1], INV_SC, c0[1]), INV_S2, bb1);
            float v2 = fmaf(fmaf(c1[2], INV_SC, c0[2]), INV_S2, bb0);
            float v3 = fmaf(fmaf(c1[3], INV_SC, c0[3]), INV_S2, bb1);
            plo = fmaf(fmaxf(v0, 0.f), w30, plo);
            plo = fmaf(fmaxf(v1, 0.f), w31, plo);
            phi = fmaf(fmaxf(v2, 0.f), w30, phi);
            phi = fmaf(fmaxf(v3, 0.f), w31, phi);
        }
        plo += __shfl_xor_sync(0xffffffffu, plo, 1);
        plo += __shfl_xor_sync(0xffffffffu, plo, 2);
        phi += __shfl_xor_sync(0xffffffffu, phi, 1);
        phi += __shfl_xor_sync(0xffffffffu, phi, 2);
        if (t == 0) {
            out[pbase + g]     = plo + bb3;
            out[pbase + g + 8] = phi + bb3;
        }
    }
}

// ---------------- launch ------------------------------------------------------
extern "C" void kernel_launch(void* const* d_in, const int* in_sizes, int n_in,
                              void* d_out, int out_size) {
    const float* coords = (const float*)d_in[0];
    const float* pxy    = (const float*)d_in[1];
    const float* pyz    = (const float*)d_in[2];
    const float* pxz    = (const float*)d_in[3];
    const float* w1     = (const float*)d_in[4];
    const float* b1     = (const float*)d_in[5];
    const float* w2     = (const float*)d_in[6];
    const float* b2     = (const float*)d_in[7];
    const float* w3     = (const float*)d_in[8];
    const float* b3     = (const float*)d_in[9];
    float* out = (float*)d_out;

    int M = in_sizes[0] / 3;       // 1048576
    int nslices = M / 16;          // 65536

    prep_kernel<<<864, 256>>>(pxy, pyz, pxz, w1, w2);

    int dev = 0, nsm = 148;
    cudaGetDevice(&dev);
    cudaDeviceGetAttribute(&nsm, cudaDevAttrMultiProcessorCount, dev);

    cudaFuncSetAttribute(fused_kernel, cudaFuncAttributeMaxDynamicSharedMemorySize, SMEM_BYTES);
    fused_kernel<<<nsm, NW * 32, SMEM_BYTES>>>(coords, b1, b2, w3, b3, out, nslices);
}